// round 14
// baseline (speedup 1.0000x reference)
#include <cuda_runtime.h>
#include <cstdint>
#include <math.h>

#define T_TOK 8192
#define D_DIM 1024
#define F_DIM 2048
#define E_EXP 8
#define KSEL  2
#define CAP   4096

// ---------------- device scratch ----------------
__device__ float    g_H  [(size_t)E_EXP * CAP * F_DIM];
__device__ float    g_Y  [(size_t)E_EXP * CAP * D_DIM];
__device__ uint32_t g_xt [(size_t)T_TOK * D_DIM];
__device__ uint32_t g_wgt[(size_t)E_EXP * D_DIM * F_DIM];
__device__ uint32_t g_wut[(size_t)E_EXP * D_DIM * F_DIM];
__device__ uint32_t g_wdt[(size_t)E_EXP * F_DIM * D_DIM];
__device__ int      g_cnt[E_EXP];
__device__ int      g_tok[E_EXP * CAP];
__device__ float    g_wt [E_EXP * CAP];
__device__ int      g_smap[T_TOK * KSEL];
__device__ double   g_psum[E_EXP];
__device__ double   g_zsum;

// ---------------- helpers ----------------
__device__ __forceinline__ uint32_t f2tf(float f) {
    uint32_t r;
    asm("cvt.rna.tf32.f32 %0, %1;" : "=r"(r) : "f"(f));
    return r;
}
__device__ __forceinline__ uint32_t s2u(const void* p) {
    uint32_t a;
    asm("{ .reg .u64 t; cvta.to.shared.u64 t, %1; cvt.u32.u64 %0, t; }" : "=r"(a) : "l"(p));
    return a;
}
#define CPA16(dst, src) \
    asm volatile("cp.async.cg.shared.global [%0], [%1], 16;" :: "r"((uint32_t)(dst)), "l"(src) : "memory")
#define CPCOMMIT() asm volatile("cp.async.commit_group;" ::: "memory")
#define CPWAITG(n) asm volatile("cp.async.wait_group %0;" :: "n"(n) : "memory")

__device__ __forceinline__ void mma8(float* d, const uint32_t* a, const uint32_t* b) {
    asm volatile("mma.sync.aligned.m16n8k8.row.col.f32.tf32.tf32.f32 "
                 "{%0,%1,%2,%3}, {%4,%5,%6,%7}, {%8,%9}, {%0,%1,%2,%3};"
                 : "+f"(d[0]), "+f"(d[1]), "+f"(d[2]), "+f"(d[3])
                 : "r"(a[0]), "r"(a[1]), "r"(a[2]), "r"(a[3]), "r"(b[0]), "r"(b[1]));
}

// SMEM strides (words). SB=136 / SB2=264: fragment-load banks all-distinct (conflict-free).
#define SA 36
#define SB 136
#define SB2 264
#define ABYTES  (128 * SA * 4)          // 18432
#define BBYTES  (32 * SB * 4)           // 17408
#define BBYTES2 (32 * SB2 * 4)          // 33792
#define STAGE1 (ABYTES + 2 * BBYTES)    // 53248
#define STAGE2 (ABYTES + BBYTES2)       // 52224
#define BUF0   1024
#define NSTG   4
#define SMEM1  (BUF0 + NSTG * STAGE1)   // 214016
#define SMEM2  (BUF0 + NSTG * STAGE2)   // 209920

// ---------------- small kernels ----------------
__global__ void init_kernel() {
    int i = threadIdx.x;
    if (i < E_EXP) { g_cnt[i] = 0; g_psum[i] = 0.0; }
    if (i == 0) g_zsum = 0.0;
}

__global__ void cvt_all(const float* __restrict__ x, const float* __restrict__ wg,
                        const float* __restrict__ wu, const float* __restrict__ wd) {
    int stride = gridDim.x * blockDim.x;
    int i0 = blockIdx.x * blockDim.x + threadIdx.x;
    const int nx = T_TOK * D_DIM / 4;
    const int nw = E_EXP * D_DIM * F_DIM / 4;
    for (int i = i0; i < nx; i += stride) {
        float4 v = ((const float4*)x)[i];
        ((uint4*)g_xt)[i] = make_uint4(f2tf(v.x), f2tf(v.y), f2tf(v.z), f2tf(v.w));
    }
    for (int i = i0; i < nw; i += stride) {
        float4 v = ((const float4*)wg)[i];
        ((uint4*)g_wgt)[i] = make_uint4(f2tf(v.x), f2tf(v.y), f2tf(v.z), f2tf(v.w));
    }
    for (int i = i0; i < nw; i += stride) {
        float4 v = ((const float4*)wu)[i];
        ((uint4*)g_wut)[i] = make_uint4(f2tf(v.x), f2tf(v.y), f2tf(v.z), f2tf(v.w));
    }
    for (int i = i0; i < nw; i += stride) {
        float4 v = ((const float4*)wd)[i];
        ((uint4*)g_wdt)[i] = make_uint4(f2tf(v.x), f2tf(v.y), f2tf(v.z), f2tf(v.w));
    }
}

__global__ void router_kernel(const float* __restrict__ x,
                              const float* __restrict__ Wr) {
    __shared__ double s_ps[E_EXP];
    __shared__ double s_zs;
    int tid = threadIdx.x;
    if (tid < E_EXP) s_ps[tid] = 0.0;
    if (tid == 0) s_zs = 0.0;
    __syncthreads();
    int lane = tid & 31, warp = tid >> 5;
    int nw = (gridDim.x * blockDim.x) >> 5;
    int gw = blockIdx.x * (blockDim.x >> 5) + warp;
    double lps[E_EXP];
#pragma unroll
    for (int e = 0; e < E_EXP; e++) lps[e] = 0.0;
    double lzs = 0.0;
    for (int t = gw; t < T_TOK; t += nw) {
        const float* xr = x + (size_t)t * D_DIM;
        float acc[E_EXP];
#pragma unroll
        for (int e = 0; e < E_EXP; e++) acc[e] = 0.f;
        for (int i = lane; i < D_DIM; i += 32) {
            float xv = xr[i];
#pragma unroll
            for (int e = 0; e < E_EXP; e++)
                acc[e] = fmaf(xv, Wr[i * E_EXP + e], acc[e]);
        }
#pragma unroll
        for (int e = 0; e < E_EXP; e++)
#pragma unroll
            for (int o = 16; o > 0; o >>= 1)
                acc[e] += __shfl_xor_sync(0xffffffffu, acc[e], o);
        if (lane == 0) {
            float m = acc[0];
#pragma unroll
            for (int e = 1; e < E_EXP; e++) m = fmaxf(m, acc[e]);
            float s = 0.f, p[E_EXP];
#pragma unroll
            for (int e = 0; e < E_EXP; e++) { p[e] = expf(acc[e] - m); s += p[e]; }
            float inv = 1.f / s;
#pragma unroll
            for (int e = 0; e < E_EXP; e++) { p[e] *= inv; lps[e] += (double)p[e]; }
            float lse = m + logf(s);
            lzs += (double)lse * (double)lse;
            int i0 = 0; float v0 = acc[0];
#pragma unroll
            for (int e = 1; e < E_EXP; e++) if (acc[e] > v0) { v0 = acc[e]; i0 = e; }
            int i1 = -1; float v1 = -INFINITY;
#pragma unroll
            for (int e = 0; e < E_EXP; e++)
                if (e != i0 && acc[e] > v1) { v1 = acc[e]; i1 = e; }
            float rinv = 1.f / (p[i0] + p[i1]);
            int p0 = atomicAdd(&g_cnt[i0], 1);
            g_tok[i0 * CAP + p0] = t; g_wt[i0 * CAP + p0] = p[i0] * rinv;
            g_smap[t * 2 + 0] = i0 * CAP + p0;
            int p1 = atomicAdd(&g_cnt[i1], 1);
            g_tok[i1 * CAP + p1] = t; g_wt[i1 * CAP + p1] = p[i1] * rinv;
            g_smap[t * 2 + 1] = i1 * CAP + p1;
        }
    }
    if (lane == 0) {
#pragma unroll
        for (int e = 0; e < E_EXP; e++) atomicAdd(&s_ps[e], lps[e]);
        atomicAdd(&s_zs, lzs);
    }
    __syncthreads();
    if (tid < E_EXP) atomicAdd(&g_psum[tid], s_ps[tid]);
    if (tid == 0) atomicAdd(&g_zsum, s_zs);
}

__global__ void finalize_kernel(float* __restrict__ out, long long out_elems) {
    if (threadIdx.x == 0 && blockIdx.x == 0) {
        double lb = 0.0;
        for (int e = 0; e < E_EXP; e++)
            lb += ((double)g_cnt[e] / (double)(T_TOK * KSEL)) * (g_psum[e] / (double)T_TOK);
        lb *= (double)E_EXP;
        double aux = 0.01 * lb + 0.001 * (g_zsum / (double)T_TOK);
        long long idx = (long long)T_TOK * D_DIM;
        if (out_elems > idx) out[idx] = (float)aux;
    }
}

__global__ void combine_kernel(float* __restrict__ out) {
    int t = blockIdx.x;
    int d4 = threadIdx.x;
    int s0 = g_smap[t * 2 + 0], s1 = g_smap[t * 2 + 1];
    float w0 = g_wt[s0], w1 = g_wt[s1];
    float4 y0 = ((const float4*)g_Y)[(size_t)s0 * (D_DIM / 4) + d4];
    float4 y1 = ((const float4*)g_Y)[(size_t)s1 * (D_DIM / 4) + d4];
    float4 r;
    r.x = w0 * y0.x + w1 * y1.x;
    r.y = w0 * y0.y + w1 * y1.y;
    r.z = w0 * y0.z + w1 * y1.z;
    r.w = w0 * y0.w + w1 * y1.w;
    ((float4*)out)[(size_t)t * (D_DIM / 4) + d4] = r;
}

// ---------------- GEMM1: 256 thr, warp grid 2x4, warp tile 64x32 (G+U), 4-stage ----------------
__global__ __launch_bounds__(256, 1)
void gemm1_mma(const float* dummy) {
    int e = blockIdx.z;
    int n = g_cnt[e];
    int row0 = blockIdx.y * 128;
    if (row0 >= n) return;
    int col0 = blockIdx.x * 128;

    extern __shared__ char smem[];
    int* toks = (int*)smem;
    uint32_t sb = s2u(smem);
    int tid = threadIdx.x, wid = tid >> 5, l = tid & 31;

    if (tid < 128) {
        int r = row0 + tid;
        toks[tid] = (r < n) ? g_tok[e * CAP + r] : g_tok[e * CAP];
    }
    __syncthreads();

    int arow = tid >> 1;
    int aseg0 = (tid & 1) * 4;
    int tok = toks[arow];
    const uint32_t* srcA = g_xt + (size_t)tok * D_DIM + aseg0 * 4;
    int brow = tid >> 3, bseg = tid & 7;
    const uint32_t* srcG = g_wgt + (size_t)e * D_DIM * F_DIM + (size_t)brow * F_DIM + col0 + bseg * 4;
    const uint32_t* srcU = g_wut + (size_t)e * D_DIM * F_DIM + (size_t)brow * F_DIM + col0 + bseg * 4;
    uint32_t adst[4], bdst[4];
#pragma unroll
    for (int j = 0; j < 4; j++) {
        adst[j] = (uint32_t)((arow * SA + (aseg0 + j) * 4) * 4);
        bdst[j] = (uint32_t)((brow * SB + bseg * 4 + j * 32) * 4);
    }

    const int NT = D_DIM / 32;  // 32

#define G1_ISSUE(c, slot) do { \
    uint32_t base_ = sb + BUF0 + (slot) * STAGE1; \
    int k0_ = (c) * 32; \
    const uint32_t* sa_ = srcA + k0_; \
    const uint32_t* sg_ = srcG + (size_t)k0_ * F_DIM; \
    const uint32_t* su_ = srcU + (size_t)k0_ * F_DIM; \
    CPA16(base_ + adst[0], sa_); \
    CPA16(base_ + adst[1], sa_ + 4); \
    CPA16(base_ + adst[2], sa_ + 8); \
    CPA16(base_ + adst[3], sa_ + 12); \
    CPA16(base_ + ABYTES + bdst[0], sg_); \
    CPA16(base_ + ABYTES + bdst[1], sg_ + 32); \
    CPA16(base_ + ABYTES + bdst[2], sg_ + 64); \
    CPA16(base_ + ABYTES + bdst[3], sg_ + 96); \
    CPA16(base_ + ABYTES + BBYTES + bdst[0], su_); \
    CPA16(base_ + ABYTES + BBYTES + bdst[1], su_ + 32); \
    CPA16(base_ + ABYTES + BBYTES + bdst[2], su_ + 64); \
    CPA16(base_ + ABYTES + BBYTES + bdst[3], su_ + 96); \
} while (0)

    float accG[4][4][4] = {}, accU[4][4][4] = {};
    int wm = wid & 1, wn = wid >> 1;
    int qr = l >> 2, qc = l & 3;

    G1_ISSUE(0, 0); CPCOMMIT();
    G1_ISSUE(1, 1); CPCOMMIT();
    G1_ISSUE(2, 2); CPCOMMIT();

    int slot = 0;
#pragma unroll 1
    for (int c = 0; c < NT; c++) {
        CPWAITG(2);
        __syncthreads();
        // issue next chunk immediately so it overlaps this chunk's compute
        if (c + 3 < NT) {
            int ws = slot + 3; if (ws >= NSTG) ws -= NSTG;
            G1_ISSUE(c + 3, ws);
        }
        CPCOMMIT();
        const uint32_t* As = (const uint32_t*)(smem + BUF0 + slot * STAGE1);
        const uint32_t* Gs = As + ABYTES / 4;
        const uint32_t* Us = As + (ABYTES + BBYTES) / 4;
#pragma unroll
        for (int ks = 0; ks < 4; ks++) {
            int kk = ks * 8;
            uint32_t af[4][4];
#pragma unroll
            for (int mt = 0; mt < 4; mt++) {
                int r0 = wm * 64 + mt * 16 + qr;
                af[mt][0] = As[r0 * SA + kk + qc];
                af[mt][1] = As[(r0 + 8) * SA + kk + qc];
                af[mt][2] = As[r0 * SA + kk + qc + 4];
                af[mt][3] = As[(r0 + 8) * SA + kk + qc + 4];
            }
            uint32_t bg[4][2], bu[4][2];
#pragma unroll
            for (int nt = 0; nt < 4; nt++) {
                int cc = wn * 32 + nt * 8 + qr;
                bg[nt][0] = Gs[(kk + qc) * SB + cc];
                bg[nt][1] = Gs[(kk + qc + 4) * SB + cc];
                bu[nt][0] = Us[(kk + qc) * SB + cc];
                bu[nt][1] = Us[(kk + qc + 4) * SB + cc];
            }
#pragma unroll
            for (int mt = 0; mt < 4; mt++)
#pragma unroll
                for (int nt = 0; nt < 4; nt++) {
                    mma8(accG[mt][nt], af[mt], bg[nt]);
                    mma8(accU[mt][nt], af[mt], bu[nt]);
                }
        }
        if (++slot == NSTG) slot = 0;
    }

#pragma unroll
    for (int mt = 0; mt < 4; mt++)
#pragma unroll
        for (int half = 0; half < 2; half++) {
            int grow = row0 + wm * 64 + mt * 16 + qr + half * 8;
            if (grow < n) {
                float* hrow = &g_H[((size_t)e * CAP + grow) * F_DIM + col0];
#pragma unroll
                for (int nt = 0; nt < 4; nt++) {
                    float g0 = accG[mt][nt][half * 2], g1 = accG[mt][nt][half * 2 + 1];
                    float u0 = accU[mt][nt][half * 2], u1 = accU[mt][nt][half * 2 + 1];
                    float h0 = __uint_as_float(f2tf(g0 / (1.f + expf(-g0)) * u0));
                    float h1 = __uint_as_float(f2tf(g1 / (1.f + expf(-g1)) * u1));
                    *(float2*)(hrow + wn * 32 + nt * 8 + qc * 2) = make_float2(h0, h1);
                }
            }
        }
}

// ---------------- GEMM2: warp tile 64x64, CTA 128x256, 4-stage ----------------
__global__ __launch_bounds__(256, 1)
void gemm2_mma(const float* dummy) {
    int e = blockIdx.z;
    int n = g_cnt[e];
    int row0 = blockIdx.y * 128;
    if (row0 >= n) return;
    int col0 = blockIdx.x * 256;

    extern __shared__ char smem[];
    uint32_t sb = s2u(smem);
    int tid = threadIdx.x, wid = tid >> 5, l = tid & 31;

    int arow = tid >> 1;
    int aseg0 = (tid & 1) * 4;
    int hr = (row0 + arow < n) ? (row0 + arow) : 0;
    const uint32_t* srcA = (const uint32_t*)g_H + ((size_t)e * CAP + hr) * F_DIM + aseg0 * 4;
    int brow = tid >> 3, bseg = tid & 7;
    const uint32_t* srcB = g_wdt + (size_t)e * F_DIM * D_DIM + (size_t)brow * D_DIM + col0 + bseg * 4;
    uint32_t adst[4], bdst[8];
#pragma unroll
    for (int j = 0; j < 4; j++)
        adst[j] = (uint32_t)((arow * SA + (aseg0 + j) * 4) * 4);
#pragma unroll
    for (int j = 0; j < 8; j++)
        bdst[j] = (uint32_t)((brow * SB2 + bseg * 4 + j * 32) * 4);

    const int NT = F_DIM / 32;  // 64

#define G2_ISSUE(c, slot) do { \
    uint32_t base_ = sb + BUF0 + (slot) * STAGE2; \
    int k0_ = (c) * 32; \
    const uint32_t* sa_ = srcA + k0_; \
    const uint32_t* sb_ = srcB + (size_t)k0_ * D_DIM; \
    CPA16(base_ + adst[0], sa_); \
    CPA16(base_ + adst[1], sa_ + 4); \
    CPA16(base_ + adst[2], sa_ + 8); \
    CPA16(base_ + adst[3], sa_ + 12); \
    CPA16(base_ + ABYTES + bdst[0], sb_); \
    CPA16(base_ + ABYTES + bdst[1], sb_ + 32); \
    CPA16(base_ + ABYTES + bdst[2], sb_ + 64); \
    CPA16(base_ + ABYTES + bdst[3], sb_ + 96); \
    CPA16(base_ + ABYTES + bdst[4], sb_ + 128); \
    CPA16(base_ + ABYTES + bdst[5], sb_ + 160); \
    CPA16(base_ + ABYTES + bdst[6], sb_ + 192); \
    CPA16(base_ + ABYTES + bdst[7], sb_ + 224); \
} while (0)

    float acc[4][8][4] = {};
    int wm = wid & 1, wn = wid >> 1;
    int qr = l >> 2, qc = l & 3;

    G2_ISSUE(0, 0); CPCOMMIT();
    G2_ISSUE(1, 1); CPCOMMIT();
    G2_ISSUE(2, 2); CPCOMMIT();

    int slot = 0;
#pragma unroll 1
    for (int c = 0; c < NT; c++) {
        CPWAITG(2);
        __syncthreads();
        if (c + 3 < NT) {
            int ws = slot + 3; if (ws >= NSTG) ws -= NSTG;
            G2_ISSUE(c + 3, ws);
        }
        CPCOMMIT();
        const uint32_t* As = (const uint32_t*)(smem + BUF0 + slot * STAGE2);
        const uint32_t* Bs = As + ABYTES / 4;
#pragma unroll
        for (int ks = 0; ks < 4; ks++) {
            int kk = ks * 8;
            uint32_t af[4][4];
#pragma unroll
            for (int mt = 0; mt < 4; mt++) {
                int r0 = wm * 64 + mt * 16 + qr;
                af[mt][0] = As[r0 * SA + kk + qc];
                af[mt][1] = As[(r0 + 8) * SA + kk + qc];
                af[mt][2] = As[r0 * SA + kk + qc + 4];
                af[mt][3] = As[(r0 + 8) * SA + kk + qc + 4];
            }
            uint32_t bf[8][2];
#pragma unroll
            for (int nt = 0; nt < 8; nt++) {
                int cc = wn * 64 + nt * 8 + qr;
                bf[nt][0] = Bs[(kk + qc) * SB2 + cc];
                bf[nt][1] = Bs[(kk + qc + 4) * SB2 + cc];
            }
#pragma unroll
            for (int mt = 0; mt < 4; mt++)
#pragma unroll
                for (int nt = 0; nt < 8; nt++)
                    mma8(acc[mt][nt], af[mt], bf[nt]);
        }
        if (++slot == NSTG) slot = 0;
    }

#pragma unroll
    for (int mt = 0; mt < 4; mt++)
#pragma unroll
        for (int half = 0; half < 2; half++) {
            int grow = row0 + wm * 64 + mt * 16 + qr + half * 8;
            if (grow < n) {
                float* yrow = &g_Y[((size_t)e * CAP + grow) * D_DIM + col0];
#pragma unroll
                for (int nt = 0; nt < 8; nt++) {
                    float v0 = acc[mt][nt][half * 2];
                    float v1 = acc[mt][nt][half * 2 + 1];
                    *(float2*)(yrow + wn * 64 + nt * 8 + qc * 2) = make_float2(v0, v1);
                }
            }
        }
}

// ---------------- launch ----------------
extern "C" void kernel_launch(void* const* d_in, const int* in_sizes, int n_in,
                              void* d_out, int out_size) {
    const float* x  = (const float*)d_in[0];
    const float* Wr = (const float*)d_in[1];
    const float* Wg = (const float*)d_in[2];
    const float* Wu = (const float*)d_in[3];
    const float* Wd = (const float*)d_in[4];
    float* out = (float*)d_out;

    cudaFuncSetAttribute(gemm1_mma, cudaFuncAttributeMaxDynamicSharedMemorySize, SMEM1);
    cudaFuncSetAttribute(gemm2_mma, cudaFuncAttributeMaxDynamicSharedMemorySize, SMEM2);

    init_kernel<<<1, 32>>>();
    cvt_all<<<2048, 256>>>(x, Wg, Wu, Wd);
    router_kernel<<<128, 256>>>(x, Wr);
    dim3 g1(F_DIM / 128, CAP / 128, E_EXP);
    gemm1_mma<<<g1, 256, SMEM1>>>(x);
    dim3 g2(D_DIM / 256, CAP / 128, E_EXP);
    gemm2_mma<<<g2, 256, SMEM2>>>(x);
    combine_kernel<<<T_TOK, D_DIM / 4>>>(out);
    finalize_kernel<<<1, 32>>>(out, (long long)out_size);
}

// round 15
// speedup vs baseline: 1.0116x; 1.0116x over previous
#include <cuda_runtime.h>
#include <cstdint>
#include <math.h>

#define T_TOK 8192
#define D_DIM 1024
#define F_DIM 2048
#define E_EXP 8
#define KSEL  2
#define CAP   4096

// ---------------- device scratch ----------------
__device__ float    g_H  [(size_t)E_EXP * CAP * F_DIM];
__device__ float    g_Y  [(size_t)E_EXP * CAP * D_DIM];
__device__ uint32_t g_xt [(size_t)T_TOK * D_DIM];
__device__ uint32_t g_wgt[(size_t)E_EXP * D_DIM * F_DIM];
__device__ uint32_t g_wut[(size_t)E_EXP * D_DIM * F_DIM];
__device__ uint32_t g_wdt[(size_t)E_EXP * F_DIM * D_DIM];
__device__ int      g_cnt[E_EXP];
__device__ int      g_tok[E_EXP * CAP];
__device__ float    g_wt [E_EXP * CAP];
__device__ int      g_smap[T_TOK * KSEL];
__device__ double   g_psum[E_EXP];
__device__ double   g_zsum;

// ---------------- helpers ----------------
__device__ __forceinline__ uint32_t f2tf(float f) {
    uint32_t r;
    asm("cvt.rna.tf32.f32 %0, %1;" : "=r"(r) : "f"(f));
    return r;
}
__device__ __forceinline__ uint32_t s2u(const void* p) {
    uint32_t a;
    asm("{ .reg .u64 t; cvta.to.shared.u64 t, %1; cvt.u32.u64 %0, t; }" : "=r"(a) : "l"(p));
    return a;
}
#define CPA16(dst, src) \
    asm volatile("cp.async.cg.shared.global [%0], [%1], 16;" :: "r"((uint32_t)(dst)), "l"(src) : "memory")
#define CPCOMMIT() asm volatile("cp.async.commit_group;" ::: "memory")
#define CPWAITG(n) asm volatile("cp.async.wait_group %0;" :: "n"(n) : "memory")

__device__ __forceinline__ void mma8(float* d, const uint32_t* a, const uint32_t* b) {
    asm volatile("mma.sync.aligned.m16n8k8.row.col.f32.tf32.tf32.f32 "
                 "{%0,%1,%2,%3}, {%4,%5,%6,%7}, {%8,%9}, {%0,%1,%2,%3};"
                 : "+f"(d[0]), "+f"(d[1]), "+f"(d[2]), "+f"(d[3])
                 : "r"(a[0]), "r"(a[1]), "r"(a[2]), "r"(a[3]), "r"(b[0]), "r"(b[1]));
}

// SMEM strides (words). SB=136 / SB2=264: fragment-load banks all-distinct (conflict-free).
#define SA 36
#define SB 136
#define SB2 264
#define ABYTES  (128 * SA * 4)          // 18432
#define BBYTES  (32 * SB * 4)           // 17408
#define BBYTES2 (32 * SB2 * 4)          // 33792
#define STAGE1 (ABYTES + 2 * BBYTES)    // 53248
#define STAGE2 (ABYTES + BBYTES2)       // 52224
#define BUF0   1024
#define NSTG   3
#define SMEM1  (BUF0 + NSTG * STAGE1)   // 160768
#define SMEM2  (BUF0 + NSTG * STAGE2)   // 157696

// ---------------- small kernels ----------------
__global__ void init_kernel() {
    int i = threadIdx.x;
    if (i < E_EXP) { g_cnt[i] = 0; g_psum[i] = 0.0; }
    if (i == 0) g_zsum = 0.0;
}

__global__ void cvt_xgu(const float* __restrict__ x, const float* __restrict__ wg,
                        const float* __restrict__ wu) {
    int stride = gridDim.x * blockDim.x;
    int i0 = blockIdx.x * blockDim.x + threadIdx.x;
    const int nx = T_TOK * D_DIM / 4;
    const int nw = E_EXP * D_DIM * F_DIM / 4;
    for (int i = i0; i < nx; i += stride) {
        float4 v = ((const float4*)x)[i];
        ((uint4*)g_xt)[i] = make_uint4(f2tf(v.x), f2tf(v.y), f2tf(v.z), f2tf(v.w));
    }
    for (int i = i0; i < nw; i += stride) {
        float4 v = ((const float4*)wg)[i];
        ((uint4*)g_wgt)[i] = make_uint4(f2tf(v.x), f2tf(v.y), f2tf(v.z), f2tf(v.w));
    }
    for (int i = i0; i < nw; i += stride) {
        float4 v = ((const float4*)wu)[i];
        ((uint4*)g_wut)[i] = make_uint4(f2tf(v.x), f2tf(v.y), f2tf(v.z), f2tf(v.w));
    }
}

__global__ void cvt_wd(const float* __restrict__ wd) {
    int stride = gridDim.x * blockDim.x;
    int i0 = blockIdx.x * blockDim.x + threadIdx.x;
    const int nw = E_EXP * D_DIM * F_DIM / 4;
    for (int i = i0; i < nw; i += stride) {
        float4 v = ((const float4*)wd)[i];
        ((uint4*)g_wdt)[i] = make_uint4(f2tf(v.x), f2tf(v.y), f2tf(v.z), f2tf(v.w));
    }
}

__global__ void router_kernel(const float* __restrict__ x,
                              const float* __restrict__ Wr) {
    __shared__ double s_ps[E_EXP];
    __shared__ double s_zs;
    int tid = threadIdx.x;
    if (tid < E_EXP) s_ps[tid] = 0.0;
    if (tid == 0) s_zs = 0.0;
    __syncthreads();
    int lane = tid & 31, warp = tid >> 5;
    int nw = (gridDim.x * blockDim.x) >> 5;
    int gw = blockIdx.x * (blockDim.x >> 5) + warp;
    double lps[E_EXP];
#pragma unroll
    for (int e = 0; e < E_EXP; e++) lps[e] = 0.0;
    double lzs = 0.0;
    for (int t = gw; t < T_TOK; t += nw) {
        const float* xr = x + (size_t)t * D_DIM;
        float acc[E_EXP];
#pragma unroll
        for (int e = 0; e < E_EXP; e++) acc[e] = 0.f;
        for (int i = lane; i < D_DIM; i += 32) {
            float xv = xr[i];
#pragma unroll
            for (int e = 0; e < E_EXP; e++)
                acc[e] = fmaf(xv, Wr[i * E_EXP + e], acc[e]);
        }
#pragma unroll
        for (int e = 0; e < E_EXP; e++)
#pragma unroll
            for (int o = 16; o > 0; o >>= 1)
                acc[e] += __shfl_xor_sync(0xffffffffu, acc[e], o);
        if (lane == 0) {
            float m = acc[0];
#pragma unroll
            for (int e = 1; e < E_EXP; e++) m = fmaxf(m, acc[e]);
            float s = 0.f, p[E_EXP];
#pragma unroll
            for (int e = 0; e < E_EXP; e++) { p[e] = expf(acc[e] - m); s += p[e]; }
            float inv = 1.f / s;
#pragma unroll
            for (int e = 0; e < E_EXP; e++) { p[e] *= inv; lps[e] += (double)p[e]; }
            float lse = m + logf(s);
            lzs += (double)lse * (double)lse;
            int i0 = 0; float v0 = acc[0];
#pragma unroll
            for (int e = 1; e < E_EXP; e++) if (acc[e] > v0) { v0 = acc[e]; i0 = e; }
            int i1 = -1; float v1 = -INFINITY;
#pragma unroll
            for (int e = 0; e < E_EXP; e++)
                if (e != i0 && acc[e] > v1) { v1 = acc[e]; i1 = e; }
            float rinv = 1.f / (p[i0] + p[i1]);
            int p0 = atomicAdd(&g_cnt[i0], 1);
            g_tok[i0 * CAP + p0] = t; g_wt[i0 * CAP + p0] = p[i0] * rinv;
            g_smap[t * 2 + 0] = i0 * CAP + p0;
            int p1 = atomicAdd(&g_cnt[i1], 1);
            g_tok[i1 * CAP + p1] = t; g_wt[i1 * CAP + p1] = p[i1] * rinv;
            g_smap[t * 2 + 1] = i1 * CAP + p1;
        }
    }
    if (lane == 0) {
#pragma unroll
        for (int e = 0; e < E_EXP; e++) atomicAdd(&s_ps[e], lps[e]);
        atomicAdd(&s_zs, lzs);
    }
    __syncthreads();
    if (tid < E_EXP) atomicAdd(&g_psum[tid], s_ps[tid]);
    if (tid == 0) atomicAdd(&g_zsum, s_zs);
}

__global__ void finalize_kernel(float* __restrict__ out, long long out_elems) {
    if (threadIdx.x == 0 && blockIdx.x == 0) {
        double lb = 0.0;
        for (int e = 0; e < E_EXP; e++)
            lb += ((double)g_cnt[e] / (double)(T_TOK * KSEL)) * (g_psum[e] / (double)T_TOK);
        lb *= (double)E_EXP;
        double aux = 0.01 * lb + 0.001 * (g_zsum / (double)T_TOK);
        long long idx = (long long)T_TOK * D_DIM;
        if (out_elems > idx) out[idx] = (float)aux;
    }
}

__global__ void combine_kernel(float* __restrict__ out) {
    int t = blockIdx.x;
    int d4 = threadIdx.x;
    int s0 = g_smap[t * 2 + 0], s1 = g_smap[t * 2 + 1];
    float w0 = g_wt[s0], w1 = g_wt[s1];
    float4 y0 = ((const float4*)g_Y)[(size_t)s0 * (D_DIM / 4) + d4];
    float4 y1 = ((const float4*)g_Y)[(size_t)s1 * (D_DIM / 4) + d4];
    float4 r;
    r.x = w0 * y0.x + w1 * y1.x;
    r.y = w0 * y0.y + w1 * y1.y;
    r.z = w0 * y0.z + w1 * y1.z;
    r.w = w0 * y0.w + w1 * y1.w;
    ((float4*)out)[(size_t)t * (D_DIM / 4) + d4] = r;
}

// ---------------- GEMM1: 256 thr, warp grid 2x4, warp tile 64x32 (G+U), 3-stage ----------------
__global__ __launch_bounds__(256, 1)
void gemm1_mma(const float* dummy) {
    int e = blockIdx.z;
    int n = g_cnt[e];
    int row0 = blockIdx.y * 128;
    if (row0 >= n) return;
    int col0 = blockIdx.x * 128;

    extern __shared__ char smem[];
    int* toks = (int*)smem;
    uint32_t sb = s2u(smem);
    int tid = threadIdx.x, wid = tid >> 5, l = tid & 31;

    if (tid < 128) {
        int r = row0 + tid;
        toks[tid] = (r < n) ? g_tok[e * CAP + r] : g_tok[e * CAP];
    }
    __syncthreads();

    int arow = tid >> 1;
    int aseg0 = (tid & 1) * 4;
    int tok = toks[arow];
    const uint32_t* srcA = g_xt + (size_t)tok * D_DIM + aseg0 * 4;
    int brow = tid >> 3, bseg = tid & 7;
    const uint32_t* srcG = g_wgt + (size_t)e * D_DIM * F_DIM + (size_t)brow * F_DIM + col0 + bseg * 4;
    const uint32_t* srcU = g_wut + (size_t)e * D_DIM * F_DIM + (size_t)brow * F_DIM + col0 + bseg * 4;
    uint32_t adst[4], bdst[4];
#pragma unroll
    for (int j = 0; j < 4; j++) {
        adst[j] = (uint32_t)((arow * SA + (aseg0 + j) * 4) * 4);
        bdst[j] = (uint32_t)((brow * SB + bseg * 4 + j * 32) * 4);
    }

    const int NT = D_DIM / 32;  // 32

#define G1_ISSUE(c, slot) do { \
    uint32_t base_ = sb + BUF0 + (slot) * STAGE1; \
    int k0_ = (c) * 32; \
    const uint32_t* sa_ = srcA + k0_; \
    const uint32_t* sg_ = srcG + (size_t)k0_ * F_DIM; \
    const uint32_t* su_ = srcU + (size_t)k0_ * F_DIM; \
    CPA16(base_ + adst[0], sa_); \
    CPA16(base_ + adst[1], sa_ + 4); \
    CPA16(base_ + adst[2], sa_ + 8); \
    CPA16(base_ + adst[3], sa_ + 12); \
    CPA16(base_ + ABYTES + bdst[0], sg_); \
    CPA16(base_ + ABYTES + bdst[1], sg_ + 32); \
    CPA16(base_ + ABYTES + bdst[2], sg_ + 64); \
    CPA16(base_ + ABYTES + bdst[3], sg_ + 96); \
    CPA16(base_ + ABYTES + BBYTES + bdst[0], su_); \
    CPA16(base_ + ABYTES + BBYTES + bdst[1], su_ + 32); \
    CPA16(base_ + ABYTES + BBYTES + bdst[2], su_ + 64); \
    CPA16(base_ + ABYTES + BBYTES + bdst[3], su_ + 96); \
} while (0)

    float accG[4][4][4] = {}, accU[4][4][4] = {};
    int wm = wid & 1, wn = wid >> 1;
    int qr = l >> 2, qc = l & 3;

    G1_ISSUE(0, 0); CPCOMMIT();
    G1_ISSUE(1, 1); CPCOMMIT();

    int slot = 0;
#pragma unroll 1
    for (int c = 0; c < NT; c++) {
        CPWAITG(1);
        __syncthreads();
        const uint32_t* As = (const uint32_t*)(smem + BUF0 + slot * STAGE1);
        const uint32_t* Gs = As + ABYTES / 4;
        const uint32_t* Us = As + (ABYTES + BBYTES) / 4;
#pragma unroll
        for (int ks = 0; ks < 4; ks++) {
            int kk = ks * 8;
            uint32_t af[4][4];
#pragma unroll
            for (int mt = 0; mt < 4; mt++) {
                int r0 = wm * 64 + mt * 16 + qr;
                af[mt][0] = As[r0 * SA + kk + qc];
                af[mt][1] = As[(r0 + 8) * SA + kk + qc];
                af[mt][2] = As[r0 * SA + kk + qc + 4];
                af[mt][3] = As[(r0 + 8) * SA + kk + qc + 4];
            }
            uint32_t bg[4][2], bu[4][2];
#pragma unroll
            for (int nt = 0; nt < 4; nt++) {
                int cc = wn * 32 + nt * 8 + qr;
                bg[nt][0] = Gs[(kk + qc) * SB + cc];
                bg[nt][1] = Gs[(kk + qc + 4) * SB + cc];
                bu[nt][0] = Us[(kk + qc) * SB + cc];
                bu[nt][1] = Us[(kk + qc + 4) * SB + cc];
            }
#pragma unroll
            for (int mt = 0; mt < 4; mt++)
#pragma unroll
                for (int nt = 0; nt < 4; nt++) {
                    mma8(accG[mt][nt], af[mt], bg[nt]);
                    mma8(accU[mt][nt], af[mt], bu[nt]);
                }
        }
        if (c + 2 < NT) {
            int ws = slot + 2; if (ws >= NSTG) ws -= NSTG;
            G1_ISSUE(c + 2, ws);
        }
        CPCOMMIT();
        if (++slot == NSTG) slot = 0;
    }

#pragma unroll
    for (int mt = 0; mt < 4; mt++)
#pragma unroll
        for (int half = 0; half < 2; half++) {
            int grow = row0 + wm * 64 + mt * 16 + qr + half * 8;
            if (grow < n) {
                float* hrow = &g_H[((size_t)e * CAP + grow) * F_DIM + col0];
#pragma unroll
                for (int nt = 0; nt < 4; nt++) {
                    float g0 = accG[mt][nt][half * 2], g1 = accG[mt][nt][half * 2 + 1];
                    float u0 = accU[mt][nt][half * 2], u1 = accU[mt][nt][half * 2 + 1];
                    float h0 = __uint_as_float(f2tf(g0 / (1.f + expf(-g0)) * u0));
                    float h1 = __uint_as_float(f2tf(g1 / (1.f + expf(-g1)) * u1));
                    *(float2*)(hrow + wn * 32 + nt * 8 + qc * 2) = make_float2(h0, h1);
                }
            }
        }
}

// ---------------- GEMM2: warp tile 64x64, CTA 128x256, 3-stage ----------------
__global__ __launch_bounds__(256, 1)
void gemm2_mma(const float* dummy) {
    int e = blockIdx.z;
    int n = g_cnt[e];
    int row0 = blockIdx.y * 128;
    if (row0 >= n) return;
    int col0 = blockIdx.x * 256;

    extern __shared__ char smem[];
    uint32_t sb = s2u(smem);
    int tid = threadIdx.x, wid = tid >> 5, l = tid & 31;

    int arow = tid >> 1;
    int aseg0 = (tid & 1) * 4;
    int hr = (row0 + arow < n) ? (row0 + arow) : 0;
    const uint32_t* srcA = (const uint32_t*)g_H + ((size_t)e * CAP + hr) * F_DIM + aseg0 * 4;
    int brow = tid >> 3, bseg = tid & 7;
    const uint32_t* srcB = g_wdt + (size_t)e * F_DIM * D_DIM + (size_t)brow * D_DIM + col0 + bseg * 4;
    uint32_t adst[4], bdst[8];
#pragma unroll
    for (int j = 0; j < 4; j++)
        adst[j] = (uint32_t)((arow * SA + (aseg0 + j) * 4) * 4);
#pragma unroll
    for (int j = 0; j < 8; j++)
        bdst[j] = (uint32_t)((brow * SB2 + bseg * 4 + j * 32) * 4);

    const int NT = F_DIM / 32;  // 64

#define G2_ISSUE(c, slot) do { \
    uint32_t base_ = sb + BUF0 + (slot) * STAGE2; \
    int k0_ = (c) * 32; \
    const uint32_t* sa_ = srcA + k0_; \
    const uint32_t* sb_ = srcB + (size_t)k0_ * D_DIM; \
    CPA16(base_ + adst[0], sa_); \
    CPA16(base_ + adst[1], sa_ + 4); \
    CPA16(base_ + adst[2], sa_ + 8); \
    CPA16(base_ + adst[3], sa_ + 12); \
    CPA16(base_ + ABYTES + bdst[0], sb_); \
    CPA16(base_ + ABYTES + bdst[1], sb_ + 32); \
    CPA16(base_ + ABYTES + bdst[2], sb_ + 64); \
    CPA16(base_ + ABYTES + bdst[3], sb_ + 96); \
    CPA16(base_ + ABYTES + bdst[4], sb_ + 128); \
    CPA16(base_ + ABYTES + bdst[5], sb_ + 160); \
    CPA16(base_ + ABYTES + bdst[6], sb_ + 192); \
    CPA16(base_ + ABYTES + bdst[7], sb_ + 224); \
} while (0)

    float acc[4][8][4] = {};
    int wm = wid & 1, wn = wid >> 1;
    int qr = l >> 2, qc = l & 3;

    G2_ISSUE(0, 0); CPCOMMIT();
    G2_ISSUE(1, 1); CPCOMMIT();

    int slot = 0;
#pragma unroll 1
    for (int c = 0; c < NT; c++) {
        CPWAITG(1);
        __syncthreads();
        const uint32_t* As = (const uint32_t*)(smem + BUF0 + slot * STAGE2);
        const uint32_t* Bs = As + ABYTES / 4;
#pragma unroll
        for (int ks = 0; ks < 4; ks++) {
            int kk = ks * 8;
            uint32_t af[4][4];
#pragma unroll
            for (int mt = 0; mt < 4; mt++) {
                int r0 = wm * 64 + mt * 16 + qr;
                af[mt][0] = As[r0 * SA + kk + qc];
                af[mt][1] = As[(r0 + 8) * SA + kk + qc];
                af[mt][2] = As[r0 * SA + kk + qc + 4];
                af[mt][3] = As[(r0 + 8) * SA + kk + qc + 4];
            }
            uint32_t bf[8][2];
#pragma unroll
            for (int nt = 0; nt < 8; nt++) {
                int cc = wn * 64 + nt * 8 + qr;
                bf[nt][0] = Bs[(kk + qc) * SB2 + cc];
                bf[nt][1] = Bs[(kk + qc + 4) * SB2 + cc];
            }
#pragma unroll
            for (int mt = 0; mt < 4; mt++)
#pragma unroll
                for (int nt = 0; nt < 8; nt++)
                    mma8(acc[mt][nt], af[mt], bf[nt]);
        }
        if (c + 2 < NT) {
            int ws = slot + 2; if (ws >= NSTG) ws -= NSTG;
            G2_ISSUE(c + 2, ws);
        }
        CPCOMMIT();
        if (++slot == NSTG) slot = 0;
    }

#pragma unroll
    for (int mt = 0; mt < 4; mt++)
#pragma unroll
        for (int half = 0; half < 2; half++) {
            int grow = row0 + wm * 64 + mt * 16 + qr + half * 8;
            if (grow < n) {
                float* yrow = &g_Y[((size_t)e * CAP + grow) * D_DIM + col0];
#pragma unroll
                for (int nt = 0; nt < 8; nt++) {
                    float v0 = acc[mt][nt][half * 2];
                    float v1 = acc[mt][nt][half * 2 + 1];
                    *(float2*)(yrow + wn * 64 + nt * 8 + qc * 2) = make_float2(v0, v1);
                }
            }
        }
}

// ---------------- launch ----------------
extern "C" void kernel_launch(void* const* d_in, const int* in_sizes, int n_in,
                              void* d_out, int out_size) {
    const float* x  = (const float*)d_in[0];
    const float* Wr = (const float*)d_in[1];
    const float* Wg = (const float*)d_in[2];
    const float* Wu = (const float*)d_in[3];
    const float* Wd = (const float*)d_in[4];
    float* out = (float*)d_out;

    static bool s_ready = false;
    static cudaStream_t s1, s2, s3;
    static cudaEvent_t e0, e1, e2, e3;
    if (!s_ready) {
        cudaStreamCreateWithFlags(&s1, cudaStreamNonBlocking);
        cudaStreamCreateWithFlags(&s2, cudaStreamNonBlocking);
        cudaStreamCreateWithFlags(&s3, cudaStreamNonBlocking);
        cudaEventCreateWithFlags(&e0, cudaEventDisableTiming);
        cudaEventCreateWithFlags(&e1, cudaEventDisableTiming);
        cudaEventCreateWithFlags(&e2, cudaEventDisableTiming);
        cudaEventCreateWithFlags(&e3, cudaEventDisableTiming);
        cudaFuncSetAttribute(gemm1_mma, cudaFuncAttributeMaxDynamicSharedMemorySize, SMEM1);
        cudaFuncSetAttribute(gemm2_mma, cudaFuncAttributeMaxDynamicSharedMemorySize, SMEM2);
        s_ready = true;
    }

    init_kernel<<<1, 32>>>();
    cudaEventRecord(e0, 0);

    cudaStreamWaitEvent(s1, e0, 0);
    cvt_xgu<<<2048, 256, 0, s1>>>(x, Wg, Wu);
    cudaEventRecord(e1, s1);

    cudaStreamWaitEvent(s2, e0, 0);
    router_kernel<<<128, 256, 0, s2>>>(x, Wr);
    cudaEventRecord(e2, s2);

    cudaStreamWaitEvent(s3, e0, 0);
    cvt_wd<<<2048, 256, 0, s3>>>(Wd);
    cudaEventRecord(e3, s3);

    cudaStreamWaitEvent(0, e1, 0);
    cudaStreamWaitEvent(0, e2, 0);
    dim3 g1(F_DIM / 128, CAP / 128, E_EXP);
    gemm1_mma<<<g1, 256, SMEM1>>>(x);

    cudaStreamWaitEvent(0, e3, 0);
    dim3 g2(D_DIM / 256, CAP / 128, E_EXP);
    gemm2_mma<<<g2, 256, SMEM2>>>(x);

    combine_kernel<<<T_TOK, D_DIM / 4>>>(out);
    finalize_kernel<<<1, 32>>>(out, (long long)out_size);
}